// round 14
// baseline (speedup 1.0000x reference)
#include <cuda_runtime.h>
#include <cuda_bf16.h>

// B=2, H=32, G=2048, C=2048, D=128, F=128
#define NPAIR 64
#define GDIM  2048
#define CDIM  2048
#define NCAT  4096
#define DDIM  128
#define FDIM  128

#define OFF_HEAP 0ULL
#define OFF_K    131072ULL
#define OFF_V    16908288ULL
#define OFF_FK   33685504ULL
#define OFF_H    50462720ULL
#define OFF_S    51511296ULL

#define CHUNKS  2
#define CHUNK_G 1024           // CDIM / CHUNKS
#define KT      16             // g rows per tile
#define NT      (CHUNK_G / KT) // 64 tiles

#define NGEMM    (NPAIR * CHUNKS)          // 128 gemm CTAs
#define NGATHER  ((NPAIR * GDIM) / 32)     // 4096 gather CTAs (4 rows/warp)

#define ROWB   272                         // padded row: 128 bf16 + 8 pad (bytes)
#define TILEB  (KT * ROWB)                 // 4352 bytes per tile buffer

typedef unsigned long long ull;

__device__ unsigned int g_order[NPAIR * NCAT];
__device__ float g_partH[(size_t)CHUNKS * NPAIR * FDIM * DDIM];   // 8 MB
__device__ float g_partS[CHUNKS * NPAIR * FDIM];
__device__ int   g_cnt[NPAIR];             // zero-init; reset by last CTA

// ---------------------------------------------------------------------------
__device__ __forceinline__ unsigned int f2key_desc(float s) {
    unsigned int u = __float_as_uint(s);
    unsigned int us = (u & 0x80000000u) ? ~u : (u | 0x80000000u);
    return ~us;
}
__device__ __forceinline__ float key2f(unsigned int hi) {
    unsigned int us = ~hi;
    unsigned int u = (us & 0x80000000u) ? (us ^ 0x80000000u) : ~us;
    return __uint_as_float(u);
}
__device__ __forceinline__ void cswap(ull& a, ull& b, bool up) {
    if ((a > b) == up) { ull t = a; a = b; b = t; }
}

// ---------------------------------------------------------------------------
// Sort: 64 CTAs, one full pair per CTA. 512 threads x 8 keys.
// in-thread j<=4; shfl j=8..128; smem only j>=256 (10 barrier stages total).
// Result ascending-by-key == descending-by-score, stable on ties.
// ---------------------------------------------------------------------------
__global__ void __launch_bounds__(512) sort_kernel(
    const float* __restrict__ heap_score,
    const float* __restrict__ win_score,
    float* __restrict__ out_heap)
{
    __shared__ ull sk[NCAT];   // 32 KB
    const int pair = blockIdx.x;
    const int tid  = threadIdx.x;

    // load 8 consecutive scores at positions p = 8*tid .. 8*tid+7
    float4 a, b;
    if (tid < 256) {
        const float4* src = (const float4*)(heap_score + (size_t)pair * GDIM);
        a = src[2 * tid]; b = src[2 * tid + 1];
    } else {
        const float4* src = (const float4*)(win_score + (size_t)pair * CDIM);
        a = src[2 * (tid - 256)]; b = src[2 * (tid - 256) + 1];
    }

    ull e[8];
    {
        const unsigned p0 = 8 * tid;
        e[0] = ((ull)f2key_desc(a.x) << 32) | (p0 + 0);
        e[1] = ((ull)f2key_desc(a.y) << 32) | (p0 + 1);
        e[2] = ((ull)f2key_desc(a.z) << 32) | (p0 + 2);
        e[3] = ((ull)f2key_desc(a.w) << 32) | (p0 + 3);
        e[4] = ((ull)f2key_desc(b.x) << 32) | (p0 + 4);
        e[5] = ((ull)f2key_desc(b.y) << 32) | (p0 + 5);
        e[6] = ((ull)f2key_desc(b.z) << 32) | (p0 + 6);
        e[7] = ((ull)f2key_desc(b.w) << 32) | (p0 + 7);
    }

    // k = 2
    cswap(e[0], e[1], true);  cswap(e[2], e[3], false);
    cswap(e[4], e[5], true);  cswap(e[6], e[7], false);
    // k = 4
    cswap(e[0], e[2], true);  cswap(e[1], e[3], true);
    cswap(e[4], e[6], false); cswap(e[5], e[7], false);
    cswap(e[0], e[1], true);  cswap(e[2], e[3], true);
    cswap(e[4], e[5], false); cswap(e[6], e[7], false);

    for (int k = 8; k <= NCAT; k <<= 1) {
        const bool up = ((tid & (k >> 3)) == 0);
        for (int j = k >> 1; j >= 8; j >>= 1) {
            if (j >= 256) {
                // smem exchange: partner thread distance j/8
                const int base = 8 * tid;
                #pragma unroll
                for (int s = 0; s < 8; ++s) sk[base + s] = e[s];
                __syncthreads();
                const int pt = (tid ^ (j >> 3)) * 8;
                const bool lower = ((tid & (j >> 3)) == 0);
                if (lower == up) {
                    #pragma unroll
                    for (int s = 0; s < 8; ++s) {
                        ull p = sk[pt + s];
                        e[s] = e[s] < p ? e[s] : p;
                    }
                } else {
                    #pragma unroll
                    for (int s = 0; s < 8; ++s) {
                        ull p = sk[pt + s];
                        e[s] = e[s] > p ? e[s] : p;
                    }
                }
                __syncthreads();
            } else {
                // in-warp shuffle: lane distance j/8 in {1..16}
                const int w = j >> 3;
                const bool lower = ((tid & w) == 0);
                #pragma unroll
                for (int s = 0; s < 8; ++s) {
                    ull p = __shfl_xor_sync(0xffffffffu, e[s], w);
                    e[s] = (lower == up) ? (e[s] < p ? e[s] : p)
                                         : (e[s] > p ? e[s] : p);
                }
            }
        }
        // j = 4, 2, 1 (in-thread), uniform direction `up`
        cswap(e[0], e[4], up); cswap(e[1], e[5], up);
        cswap(e[2], e[6], up); cswap(e[3], e[7], up);
        cswap(e[0], e[2], up); cswap(e[1], e[3], up);
        cswap(e[4], e[6], up); cswap(e[5], e[7], up);
        cswap(e[0], e[1], up); cswap(e[2], e[3], up);
        cswap(e[4], e[5], up); cswap(e[6], e[7], up);
    }

    // store order (8 consecutive indices) and heap scores (top half)
    {
        uint4 o0 = make_uint4((unsigned)e[0], (unsigned)e[1],
                              (unsigned)e[2], (unsigned)e[3]);
        uint4 o1 = make_uint4((unsigned)e[4], (unsigned)e[5],
                              (unsigned)e[6], (unsigned)e[7]);
        uint4* dst = (uint4*)(g_order + pair * NCAT + 8 * tid);
        dst[0] = o0; dst[1] = o1;
    }
    if (tid < 256) {
        float4 h0, h1;
        h0.x = key2f((unsigned)(e[0] >> 32));
        h0.y = key2f((unsigned)(e[1] >> 32));
        h0.z = key2f((unsigned)(e[2] >> 32));
        h0.w = key2f((unsigned)(e[3] >> 32));
        h1.x = key2f((unsigned)(e[4] >> 32));
        h1.y = key2f((unsigned)(e[5] >> 32));
        h1.z = key2f((unsigned)(e[6] >> 32));
        h1.w = key2f((unsigned)(e[7] >> 32));
        float4* dst = (float4*)(out_heap + (size_t)pair * GDIM + 8 * tid);
        dst[0] = h0; dst[1] = h1;
    }
}

// ---------------------------------------------------------------------------
// mma helpers
// ---------------------------------------------------------------------------
__device__ __forceinline__ void ldsm4t(unsigned r[4], unsigned addr) {
    asm volatile(
        "ldmatrix.sync.aligned.m8n8.x4.trans.shared.b16 {%0,%1,%2,%3}, [%4];"
        : "=r"(r[0]), "=r"(r[1]), "=r"(r[2]), "=r"(r[3]) : "r"(addr));
}
__device__ __forceinline__ void mma16816(float c[4], const unsigned a[4],
                                         unsigned b0, unsigned b1) {
    asm volatile(
        "mma.sync.aligned.m16n8k16.row.col.f32.bf16.bf16.f32 "
        "{%0,%1,%2,%3}, {%4,%5,%6,%7}, {%8,%9}, {%0,%1,%2,%3};"
        : "+f"(c[0]), "+f"(c[1]), "+f"(c[2]), "+f"(c[3])
        : "r"(a[0]), "r"(a[1]), "r"(a[2]), "r"(a[3]), "r"(b0), "r"(b1));
}
__device__ __forceinline__ float bf16bits2f(unsigned short u) {
    return __uint_as_float(((unsigned)u) << 16);
}

// ---------------------------------------------------------------------------
// GEMM kernel (128 CTAs, CHUNKS=2): tensor-core bf16 3-pass split-K +
// in-kernel deterministic last-CTA reduction.
// ---------------------------------------------------------------------------
__global__ void __launch_bounds__(256, 2) gemm_kernel(
    const float* __restrict__ V_top, const float* __restrict__ FK_top,
    const float* __restrict__ V_win, const float* __restrict__ FK_win,
    float* __restrict__ out)
{
    __shared__ __align__(16) unsigned char smAh[2][TILEB];  // FK hi [g][f] bf16
    __shared__ __align__(16) unsigned char smAl[2][TILEB];  // FK lo
    __shared__ __align__(16) unsigned char smBh[2][TILEB];  // V  hi [g][d]
    __shared__ __align__(16) unsigned char smBl[2][TILEB];  // V  lo
    __shared__ unsigned s_idx[CHUNK_G];                     // 4 KB idx prefetch
    __shared__ int s_is_last;

    const int bid = blockIdx.x;
    const int tid = threadIdx.x;

    const int pair  = bid & (NPAIR - 1);
    const int chunk = bid >> 6;
    const int obase = pair * NCAT + GDIM + chunk * CHUNK_G;

    const int lane = tid & 31;
    const int warp = tid >> 5;            // m strip: f = warp*16..+15
    const int gg   = tid >> 4;            // staging row 0..15
    const int cc   = tid & 15;            // staging col group

    const int kk  = lane & 7;
    const int sel = lane >> 3;
    const unsigned offA = (unsigned)(((sel >> 1) * 8 + kk) * ROWB
                                     + (warp * 16 + (sel & 1) * 8) * 2);
    const unsigned offB = (unsigned)(((sel & 1) * 8 + kk) * ROWB
                                     + ((sel >> 1) * 8) * 2);

    const unsigned baseAh = (unsigned)__cvta_generic_to_shared(&smAh[0][0]);
    const unsigned baseAl = (unsigned)__cvta_generic_to_shared(&smAl[0][0]);
    const unsigned baseBh = (unsigned)__cvta_generic_to_shared(&smBh[0][0]);
    const unsigned baseBl = (unsigned)__cvta_generic_to_shared(&smBl[0][0]);

    // prefetch ALL chunk indices (off the per-tile critical path)
    #pragma unroll
    for (int t = 0; t < CHUNK_G / 256; ++t)
        s_idx[tid + t * 256] = g_order[obase + tid + t * 256];
    __syncthreads();

    float acc[16][4];
    #pragma unroll
    for (int i = 0; i < 16; ++i)
        #pragma unroll
        for (int j = 0; j < 4; ++j) acc[i][j] = 0.0f;
    float s_local = 0.0f;

    struct Stage { float4 f0, f1, v0, v1; };
    auto stage_ldg = [&](int kt) -> Stage {
        const unsigned idx = s_idx[kt * KT + gg];
        const float *fsrc, *vsrc;
        if (idx < GDIM) {
            const size_t r = (size_t)pair * GDIM + idx;
            fsrc = FK_top + r * FDIM;  vsrc = V_top + r * DDIM;
        } else {
            const size_t r = (size_t)pair * CDIM + (idx - GDIM);
            fsrc = FK_win + r * FDIM;  vsrc = V_win + r * DDIM;
        }
        Stage s;
        s.f0 = *(const float4*)(fsrc + 4 * cc);
        s.f1 = *(const float4*)(fsrc + 64 + 4 * cc);
        s.v0 = *(const float4*)(vsrc + 4 * cc);
        s.v1 = *(const float4*)(vsrc + 64 + 4 * cc);
        return s;
    };
    auto cvt_sts = [&](unsigned char* hi_buf, unsigned char* lo_buf,
                       float4 a, int byteoff) {
        __nv_bfloat162 h01 = __floats2bfloat162_rn(a.x, a.y);
        __nv_bfloat162 h23 = __floats2bfloat162_rn(a.z, a.w);
        float r0 = __low2float(h01), r1 = __high2float(h01);
        float r2 = __low2float(h23), r3 = __high2float(h23);
        __nv_bfloat162 l01 = __floats2bfloat162_rn(a.x - r0, a.y - r1);
        __nv_bfloat162 l23 = __floats2bfloat162_rn(a.z - r2, a.w - r3);
        *(uint2*)(hi_buf + byteoff) =
            make_uint2(*(unsigned*)&h01, *(unsigned*)&h23);
        *(uint2*)(lo_buf + byteoff) =
            make_uint2(*(unsigned*)&l01, *(unsigned*)&l23);
    };
    auto stage_sts = [&](int buf, const Stage& s) {
        const int bo = gg * ROWB + cc * 8;
        cvt_sts(smAh[buf], smAl[buf], s.f0, bo);
        cvt_sts(smAh[buf], smAl[buf], s.f1, bo + 128);
        cvt_sts(smBh[buf], smBl[buf], s.v0, bo);
        cvt_sts(smBh[buf], smBl[buf], s.v1, bo + 128);
    };

    Stage st = stage_ldg(0);
    stage_sts(0, st);

    for (int kt = 0; kt < NT; ++kt) {
        const int buf = kt & 1;
        if (kt + 1 < NT) st = stage_ldg(kt + 1);   // LDG early
        __syncthreads();                           // tile kt smem ready

        const unsigned bufo = (unsigned)(buf * TILEB);
        unsigned Ah[4], Al[4];
        ldsm4t(Ah, baseAh + bufo + offA);
        ldsm4t(Al, baseAl + bufo + offA);

        #pragma unroll
        for (int np = 0; np < 8; ++np) {
            unsigned Bh[4], Bl[4];
            const unsigned nb = (unsigned)(np * 32);
            ldsm4t(Bh, baseBh + bufo + offB + nb);
            ldsm4t(Bl, baseBl + bufo + offB + nb);
            mma16816(acc[2 * np],     Ah, Bh[0], Bh[1]);
            mma16816(acc[2 * np + 1], Ah, Bh[2], Bh[3]);
            mma16816(acc[2 * np],     Ah, Bl[0], Bl[1]);
            mma16816(acc[2 * np + 1], Ah, Bl[2], Bl[3]);
            mma16816(acc[2 * np],     Al, Bh[0], Bh[1]);
            mma16816(acc[2 * np + 1], Al, Bh[2], Bh[3]);
        }

        {
            const int f = tid & 127;
            const unsigned char* src = (tid < 128) ? smAh[buf] : smAl[buf];
            #pragma unroll
            for (int g = 0; g < KT; ++g)
                s_local += bf16bits2f(*(const unsigned short*)
                                      (src + g * ROWB + f * 2));
        }

        if (kt + 1 < NT) stage_sts(buf ^ 1, st);
    }

    // write split-K partials
    float* Hp = g_partH + ((size_t)(chunk * NPAIR + pair)) * (FDIM * DDIM);
    {
        const int gid = lane >> 2, tg = lane & 3;
        const int f0 = warp * 16 + gid;
        #pragma unroll
        for (int nt = 0; nt < 16; ++nt) {
            const int d0 = nt * 8 + 2 * tg;
            *(float2*)&Hp[f0 * DDIM + d0]       =
                make_float2(acc[nt][0], acc[nt][1]);
            *(float2*)&Hp[(f0 + 8) * DDIM + d0] =
                make_float2(acc[nt][2], acc[nt][3]);
        }
    }
    __syncthreads();                 // smem reads done; reuse as scratch
    {
        float* Ssc = (float*)&smAh[0][0];
        Ssc[tid] = s_local;
        __syncthreads();
        if (tid < 128)
            g_partS[(chunk * NPAIR + pair) * FDIM + tid] =
                Ssc[tid] + Ssc[tid + 128];
    }

    // deterministic in-kernel reduction by the last-arriving chunk CTA
    __threadfence();
    if (tid == 0)
        s_is_last = (atomicAdd(&g_cnt[pair], 1) == CHUNKS - 1);
    __syncthreads();
    if (s_is_last) {
        __threadfence();
        const size_t NHp = (size_t)FDIM * DDIM;
        const float4* p0 = (const float4*)(g_partH + (0 * NPAIR + pair) * NHp);
        const float4* p1 = (const float4*)(g_partH + (1 * NPAIR + pair) * NHp);
        float4* Ho = (float4*)(out + OFF_H + (size_t)pair * NHp);
        for (int i = tid; i < (int)(NHp / 4); i += 256) {
            float4 a = p0[i], b = p1[i];
            float4 r;
            r.x = a.x + b.x;  r.y = a.y + b.y;
            r.z = a.z + b.z;  r.w = a.w + b.w;
            Ho[i] = r;
        }
        if (tid < FDIM) {
            float s = 0.0f;
            #pragma unroll
            for (int c2 = 0; c2 < CHUNKS; ++c2)
                s += g_partS[(c2 * NPAIR + pair) * FDIM + tid];
            out[OFF_S + pair * FDIM + tid] = s;
        }
        if (tid == 0) g_cnt[pair] = 0;   // reset for next graph replay
    }
}

// ---------------------------------------------------------------------------
// Gather kernel (lean registers -> 3 CTAs/SM, 24 warps): 4 rows/warp.
// ---------------------------------------------------------------------------
__global__ void __launch_bounds__(256, 3) gather_kernel(
    const float* __restrict__ K_top, const float* __restrict__ V_top,
    const float* __restrict__ FK_top,
    const float* __restrict__ K_win, const float* __restrict__ V_win,
    const float* __restrict__ FK_win,
    float* __restrict__ out)
{
    const int tid  = threadIdx.x;
    const int warp = tid >> 5;
    const int lane = tid & 31;
    const int rowid0 = (blockIdx.x * 8 + warp) * 4;   // 4 consecutive rows
    const int pair   = rowid0 >> 11;
    const int gbase  = pair * NCAT + (rowid0 & (GDIM - 1));

    const float4 *ks[4], *vs[4], *fs[4];
    #pragma unroll
    for (int r = 0; r < 4; ++r) {
        const unsigned idx = g_order[gbase + r];
        if (idx < GDIM) {
            const size_t rr = (size_t)pair * GDIM + idx;
            ks[r] = (const float4*)(K_top + rr * 128);
            vs[r] = (const float4*)(V_top + rr * 128);
            fs[r] = (const float4*)(FK_top + rr * 128);
        } else {
            const size_t rr = (size_t)pair * CDIM + (idx - GDIM);
            ks[r] = (const float4*)(K_win + rr * 128);
            vs[r] = (const float4*)(V_win + rr * 128);
            fs[r] = (const float4*)(FK_win + rr * 128);
        }
    }
    float4 rk[4], rv[4], rf[4];
    #pragma unroll
    for (int r = 0; r < 4; ++r) {   // 12 independent loads in flight
        rk[r] = ks[r][lane]; rv[r] = vs[r][lane]; rf[r] = fs[r][lane];
    }
    #pragma unroll
    for (int r = 0; r < 4; ++r) {
        ((float4*)(out + OFF_K  + (size_t)(rowid0 + r) * 128))[lane] = rk[r];
        ((float4*)(out + OFF_V  + (size_t)(rowid0 + r) * 128))[lane] = rv[r];
        ((float4*)(out + OFF_FK + (size_t)(rowid0 + r) * 128))[lane] = rf[r];
    }
}

// ---------------------------------------------------------------------------
extern "C" void kernel_launch(void* const* d_in, const int* in_sizes, int n_in,
                              void* d_out, int out_size)
{
    const float* K_top      = (const float*)d_in[0];
    const float* V_top      = (const float*)d_in[1];
    const float* FK_top     = (const float*)d_in[2];
    const float* heap_score = (const float*)d_in[3];
    const float* K_win      = (const float*)d_in[4];
    const float* V_win      = (const float*)d_in[5];
    const float* FK_win     = (const float*)d_in[6];
    const float* win_score  = (const float*)d_in[7];
    float* out = (float*)d_out;

    cudaStream_t s2;
    cudaStreamCreateWithFlags(&s2, cudaStreamNonBlocking);
    cudaEvent_t e1, e2;
    cudaEventCreateWithFlags(&e1, cudaEventDisableTiming);
    cudaEventCreateWithFlags(&e2, cudaEventDisableTiming);

    sort_kernel<<<NPAIR, 512>>>(heap_score, win_score, out + OFF_HEAP);

    // fork: gemm on s2, gather on the captured (default) stream — concurrent
    cudaEventRecord(e1, 0);
    cudaStreamWaitEvent(s2, e1, 0);
    gemm_kernel<<<NGEMM, 256, 0, s2>>>(V_top, FK_top, V_win, FK_win, out);
    gather_kernel<<<NGATHER, 256>>>(K_top, V_top, FK_top,
                                    K_win, V_win, FK_win, out);
    // join
    cudaEventRecord(e2, s2);
    cudaStreamWaitEvent(0, e2, 0);
}

// round 15
// speedup vs baseline: 1.1905x; 1.1905x over previous
#include <cuda_runtime.h>
#include <cuda_bf16.h>

// B=2, H=32, G=2048, C=2048, D=128, F=128
#define NPAIR 64
#define GDIM  2048
#define CDIM  2048
#define NCAT  4096
#define DDIM  128
#define FDIM  128

#define OFF_HEAP 0ULL
#define OFF_K    131072ULL
#define OFF_V    16908288ULL
#define OFF_FK   33685504ULL
#define OFF_H    50462720ULL
#define OFF_S    51511296ULL

#define CHUNKS  4
#define CHUNK_G 512            // CDIM / CHUNKS
#define KT      16             // g rows per tile
#define NT      (CHUNK_G / KT) // 32 tiles

#define NGEMM    (NPAIR * CHUNKS)          // 256 gemm CTAs
#define NGATHER  ((NPAIR * GDIM) / 32)     // 4096 gather CTAs (4 rows/warp)

#define ROWB   272                         // padded row: 128 bf16 + 8 pad (bytes)
#define TILEB  (KT * ROWB)                 // 4352 bytes per tile buffer

typedef unsigned long long ull;

__device__ unsigned int g_order[NPAIR * NCAT];
__device__ float g_partH[(size_t)CHUNKS * NPAIR * FDIM * DDIM];   // 16 MB
__device__ float g_partS[CHUNKS * NPAIR * FDIM];
__device__ int   g_cnt[NPAIR];             // zero-init; reset by last CTA

// ---------------------------------------------------------------------------
__device__ __forceinline__ unsigned int f2key_desc(float s) {
    unsigned int u = __float_as_uint(s);
    unsigned int us = (u & 0x80000000u) ? ~u : (u | 0x80000000u);
    return ~us;
}
__device__ __forceinline__ float key2f(unsigned int hi) {
    unsigned int us = ~hi;
    unsigned int u = (us & 0x80000000u) ? (us ^ 0x80000000u) : ~us;
    return __uint_as_float(u);
}
__device__ __forceinline__ void cswap(ull& a, ull& b, bool up) {
    if ((a > b) == up) { ull t = a; a = b; b = t; }
}
__device__ __forceinline__ ull dsmem_ld64(unsigned my_smem_addr, unsigned peer_rank) {
    unsigned remote;
    asm("mapa.shared::cluster.u32 %0, %1, %2;"
        : "=r"(remote) : "r"(my_smem_addr), "r"(peer_rank));
    ull v;
    asm volatile("ld.shared::cluster.b64 %0, [%1];" : "=l"(v) : "r"(remote));
    return v;
}
// streaming (evict-first) stores for write-once data
__device__ __forceinline__ void stcs128(float* p, float4 v) {
    asm volatile("st.global.cs.v4.f32 [%0], {%1,%2,%3,%4};"
                 :: "l"(p), "f"(v.x), "f"(v.y), "f"(v.z), "f"(v.w) : "memory");
}

// ---------------------------------------------------------------------------
// Cluster sort: 128 CTAs in 64 clusters of 2; half-sort, DSMEM exchange,
// local merge. (Validated R11-R13.)
// ---------------------------------------------------------------------------
__global__ void __launch_bounds__(512) __cluster_dims__(2, 1, 1)
sort_kernel(const float* __restrict__ heap_score,
            const float* __restrict__ win_score,
            float* __restrict__ out_heap)
{
    __shared__ ull sk[2048];   // 16 KB
    const int pair = blockIdx.x >> 1;
    const int half = blockIdx.x & 1;     // == cluster ctarank
    const int tid  = threadIdx.x;
    const bool desc = (half == 1);

    float4 sc = (half == 0)
        ? ((const float4*)(heap_score + (size_t)pair * GDIM))[tid]
        : ((const float4*)(win_score  + (size_t)pair * CDIM))[tid];

    ull e[4];
    {
        const int p = half * 2048 + 4 * tid;
        e[0] = ((ull)f2key_desc(sc.x) << 32) | (unsigned)(p + 0);
        e[1] = ((ull)f2key_desc(sc.y) << 32) | (unsigned)(p + 1);
        e[2] = ((ull)f2key_desc(sc.z) << 32) | (unsigned)(p + 2);
        e[3] = ((ull)f2key_desc(sc.w) << 32) | (unsigned)(p + 3);
    }

    cswap(e[0], e[1], !desc);
    cswap(e[2], e[3], desc);

    for (int k = 4; k <= 2048; k <<= 1) {
        const bool up = (((tid & (k >> 2)) == 0) != desc);
        for (int j = k >> 1; j >= 4; j >>= 1) {
            if (j >= 128) {
                const int base = 4 * tid;
                sk[base + 0] = e[0]; sk[base + 1] = e[1];
                sk[base + 2] = e[2]; sk[base + 3] = e[3];
                __syncthreads();
                const int pt = (tid ^ (j >> 2)) * 4;
                const bool lower = ((tid & (j >> 2)) == 0);
                ull p0 = sk[pt], p1 = sk[pt + 1], p2 = sk[pt + 2], p3 = sk[pt + 3];
                if (lower == up) {
                    e[0] = e[0] < p0 ? e[0] : p0;  e[1] = e[1] < p1 ? e[1] : p1;
                    e[2] = e[2] < p2 ? e[2] : p2;  e[3] = e[3] < p3 ? e[3] : p3;
                } else {
                    e[0] = e[0] > p0 ? e[0] : p0;  e[1] = e[1] > p1 ? e[1] : p1;
                    e[2] = e[2] > p2 ? e[2] : p2;  e[3] = e[3] > p3 ? e[3] : p3;
                }
                __syncthreads();
            } else {
                const int w = j >> 2;
                const bool lower = ((tid & w) == 0);
                #pragma unroll
                for (int s = 0; s < 4; ++s) {
                    ull p = __shfl_xor_sync(0xffffffffu, e[s], w);
                    e[s] = (lower == up) ? (e[s] < p ? e[s] : p)
                                         : (e[s] > p ? e[s] : p);
                }
            }
        }
        cswap(e[0], e[2], up); cswap(e[1], e[3], up);
        cswap(e[0], e[1], up); cswap(e[2], e[3], up);
    }

    {
        const int base = 4 * tid;
        sk[base + 0] = e[0]; sk[base + 1] = e[1];
        sk[base + 2] = e[2]; sk[base + 3] = e[3];
    }
    asm volatile("barrier.cluster.arrive.aligned;" ::: "memory");
    asm volatile("barrier.cluster.wait.aligned;" ::: "memory");
    {
        const unsigned peer = (unsigned)(half ^ 1);
        #pragma unroll
        for (int s = 0; s < 4; ++s) {
            const unsigned a =
                (unsigned)__cvta_generic_to_shared(&sk[4 * tid + s]);
            ull p = dsmem_ld64(a, peer);
            if (half == 0) e[s] = e[s] < p ? e[s] : p;
            else           e[s] = e[s] > p ? e[s] : p;
        }
    }
    asm volatile("barrier.cluster.arrive.aligned;" ::: "memory");
    asm volatile("barrier.cluster.wait.aligned;" ::: "memory");

    #pragma unroll
    for (int j = 1024; j >= 128; j >>= 1) {
        const int base = 4 * tid;
        sk[base + 0] = e[0]; sk[base + 1] = e[1];
        sk[base + 2] = e[2]; sk[base + 3] = e[3];
        __syncthreads();
        const int pt = (tid ^ (j >> 2)) * 4;
        const bool lower = ((tid & (j >> 2)) == 0);
        ull q0 = sk[pt], q1 = sk[pt + 1], q2 = sk[pt + 2], q3 = sk[pt + 3];
        if (lower) {
            e[0] = e[0] < q0 ? e[0] : q0;  e[1] = e[1] < q1 ? e[1] : q1;
            e[2] = e[2] < q2 ? e[2] : q2;  e[3] = e[3] < q3 ? e[3] : q3;
        } else {
            e[0] = e[0] > q0 ? e[0] : q0;  e[1] = e[1] > q1 ? e[1] : q1;
            e[2] = e[2] > q2 ? e[2] : q2;  e[3] = e[3] > q3 ? e[3] : q3;
        }
        __syncthreads();
    }
    #pragma unroll
    for (int j = 64; j >= 4; j >>= 1) {
        const int w = j >> 2;
        const bool lower = ((tid & w) == 0);
        #pragma unroll
        for (int s = 0; s < 4; ++s) {
            ull q = __shfl_xor_sync(0xffffffffu, e[s], w);
            e[s] = lower ? (e[s] < q ? e[s] : q) : (e[s] > q ? e[s] : q);
        }
    }
    cswap(e[0], e[2], true); cswap(e[1], e[3], true);
    cswap(e[0], e[1], true); cswap(e[2], e[3], true);

    const int mybase = pair * NCAT + half * 2048 + 4 * tid;
    g_order[mybase + 0] = (unsigned)e[0];
    g_order[mybase + 1] = (unsigned)e[1];
    g_order[mybase + 2] = (unsigned)e[2];
    g_order[mybase + 3] = (unsigned)e[3];
    if (half == 0) {
        float4 hs;
        hs.x = key2f((unsigned)(e[0] >> 32));
        hs.y = key2f((unsigned)(e[1] >> 32));
        hs.z = key2f((unsigned)(e[2] >> 32));
        hs.w = key2f((unsigned)(e[3] >> 32));
        ((float4*)(out_heap + (size_t)pair * GDIM))[tid] = hs;
    }
    // NOTE: no final cluster barrier needed — after the 2nd cluster barrier
    // no CTA reads peer smem again.
}

// ---------------------------------------------------------------------------
// mma helpers
// ---------------------------------------------------------------------------
__device__ __forceinline__ void ldsm4t(unsigned r[4], unsigned addr) {
    asm volatile(
        "ldmatrix.sync.aligned.m8n8.x4.trans.shared.b16 {%0,%1,%2,%3}, [%4];"
        : "=r"(r[0]), "=r"(r[1]), "=r"(r[2]), "=r"(r[3]) : "r"(addr));
}
__device__ __forceinline__ void mma16816(float c[4], const unsigned a[4],
                                         unsigned b0, unsigned b1) {
    asm volatile(
        "mma.sync.aligned.m16n8k16.row.col.f32.bf16.bf16.f32 "
        "{%0,%1,%2,%3}, {%4,%5,%6,%7}, {%8,%9}, {%0,%1,%2,%3};"
        : "+f"(c[0]), "+f"(c[1]), "+f"(c[2]), "+f"(c[3])
        : "r"(a[0]), "r"(a[1]), "r"(a[2]), "r"(a[3]), "r"(b0), "r"(b1));
}
__device__ __forceinline__ float bf16bits2f(unsigned short u) {
    return __uint_as_float(((unsigned)u) << 16);
}

// ---------------------------------------------------------------------------
// GEMM kernel (256 CTAs, CHUNKS=4): tensor-core bf16 3-pass split-K +
// in-kernel deterministic last-CTA reduction.
// ---------------------------------------------------------------------------
__global__ void __launch_bounds__(256, 2) gemm_kernel(
    const float* __restrict__ V_top, const float* __restrict__ FK_top,
    const float* __restrict__ V_win, const float* __restrict__ FK_win,
    float* __restrict__ out)
{
    __shared__ __align__(16) unsigned char smAh[2][TILEB];  // FK hi [g][f] bf16
    __shared__ __align__(16) unsigned char smAl[2][TILEB];  // FK lo
    __shared__ __align__(16) unsigned char smBh[2][TILEB];  // V  hi [g][d]
    __shared__ __align__(16) unsigned char smBl[2][TILEB];  // V  lo
    __shared__ unsigned s_idx[CHUNK_G];                     // 2 KB idx prefetch
    __shared__ int s_is_last;

    const int bid = blockIdx.x;
    const int tid = threadIdx.x;

    const int pair  = bid & (NPAIR - 1);
    const int chunk = bid >> 6;
    const int obase = pair * NCAT + GDIM + chunk * CHUNK_G;

    const int lane = tid & 31;
    const int warp = tid >> 5;            // m strip: f = warp*16..+15
    const int gg   = tid >> 4;            // staging row 0..15
    const int cc   = tid & 15;            // staging col group

    const int kk  = lane & 7;
    const int sel = lane >> 3;
    const unsigned offA = (unsigned)(((sel >> 1) * 8 + kk) * ROWB
                                     + (warp * 16 + (sel & 1) * 8) * 2);
    const unsigned offB = (unsigned)(((sel & 1) * 8 + kk) * ROWB
                                     + ((sel >> 1) * 8) * 2);

    const unsigned baseAh = (unsigned)__cvta_generic_to_shared(&smAh[0][0]);
    const unsigned baseAl = (unsigned)__cvta_generic_to_shared(&smAl[0][0]);
    const unsigned baseBh = (unsigned)__cvta_generic_to_shared(&smBh[0][0]);
    const unsigned baseBl = (unsigned)__cvta_generic_to_shared(&smBl[0][0]);

    // prefetch ALL chunk indices (off the per-tile critical path)
    s_idx[tid]       = g_order[obase + tid];
    s_idx[tid + 256] = g_order[obase + tid + 256];
    __syncthreads();

    float acc[16][4];
    #pragma unroll
    for (int i = 0; i < 16; ++i)
        #pragma unroll
        for (int j = 0; j < 4; ++j) acc[i][j] = 0.0f;
    float s_local = 0.0f;

    struct Stage { float4 f0, f1, v0, v1; };
    auto stage_ldg = [&](int kt) -> Stage {
        const unsigned idx = s_idx[kt * KT + gg];
        const float *fsrc, *vsrc;
        if (idx < GDIM) {
            const size_t r = (size_t)pair * GDIM + idx;
            fsrc = FK_top + r * FDIM;  vsrc = V_top + r * DDIM;
        } else {
            const size_t r = (size_t)pair * CDIM + (idx - GDIM);
            fsrc = FK_win + r * FDIM;  vsrc = V_win + r * DDIM;
        }
        Stage s;
        s.f0 = *(const float4*)(fsrc + 4 * cc);
        s.f1 = *(const float4*)(fsrc + 64 + 4 * cc);
        s.v0 = *(const float4*)(vsrc + 4 * cc);
        s.v1 = *(const float4*)(vsrc + 64 + 4 * cc);
        return s;
    };
    auto cvt_sts = [&](unsigned char* hi_buf, unsigned char* lo_buf,
                       float4 a, int byteoff) {
        __nv_bfloat162 h01 = __floats2bfloat162_rn(a.x, a.y);
        __nv_bfloat162 h23 = __floats2bfloat162_rn(a.z, a.w);
        float r0 = __low2float(h01), r1 = __high2float(h01);
        float r2 = __low2float(h23), r3 = __high2float(h23);
        __nv_bfloat162 l01 = __floats2bfloat162_rn(a.x - r0, a.y - r1);
        __nv_bfloat162 l23 = __floats2bfloat162_rn(a.z - r2, a.w - r3);
        *(uint2*)(hi_buf + byteoff) =
            make_uint2(*(unsigned*)&h01, *(unsigned*)&h23);
        *(uint2*)(lo_buf + byteoff) =
            make_uint2(*(unsigned*)&l01, *(unsigned*)&l23);
    };
    auto stage_sts = [&](int buf, const Stage& s) {
        const int bo = gg * ROWB + cc * 8;
        cvt_sts(smAh[buf], smAl[buf], s.f0, bo);
        cvt_sts(smAh[buf], smAl[buf], s.f1, bo + 128);
        cvt_sts(smBh[buf], smBl[buf], s.v0, bo);
        cvt_sts(smBh[buf], smBl[buf], s.v1, bo + 128);
    };

    Stage st = stage_ldg(0);
    stage_sts(0, st);

    for (int kt = 0; kt < NT; ++kt) {
        const int buf = kt & 1;
        if (kt + 1 < NT) st = stage_ldg(kt + 1);   // LDG early
        __syncthreads();                           // tile kt smem ready

        const unsigned bufo = (unsigned)(buf * TILEB);
        unsigned Ah[4], Al[4];
        ldsm4t(Ah, baseAh + bufo + offA);
        ldsm4t(Al, baseAl + bufo + offA);

        #pragma unroll
        for (int np = 0; np < 8; ++np) {
            unsigned Bh[4], Bl[4];
            const unsigned nb = (unsigned)(np * 32);
            ldsm4t(Bh, baseBh + bufo + offB + nb);
            ldsm4t(Bl, baseBl + bufo + offB + nb);
            mma16816(acc[2 * np],     Ah, Bh[0], Bh[1]);
            mma16816(acc[2 * np + 1], Ah, Bh[2], Bh[3]);
            mma16816(acc[2 * np],     Ah, Bl[0], Bl[1]);
            mma16816(acc[2 * np + 1], Ah, Bl[2], Bl[3]);
            mma16816(acc[2 * np],     Al, Bh[0], Bh[1]);
            mma16816(acc[2 * np + 1], Al, Bh[2], Bh[3]);
        }

        {
            const int f = tid & 127;
            const unsigned char* src = (tid < 128) ? smAh[buf] : smAl[buf];
            #pragma unroll
            for (int g = 0; g < KT; ++g)
                s_local += bf16bits2f(*(const unsigned short*)
                                      (src + g * ROWB + f * 2));
        }

        if (kt + 1 < NT) stage_sts(buf ^ 1, st);
    }

    // write split-K partials (normal stores: re-read once by last CTA via L2)
    float* Hp = g_partH + ((size_t)(chunk * NPAIR + pair)) * (FDIM * DDIM);
    {
        const int gid = lane >> 2, tg = lane & 3;
        const int f0 = warp * 16 + gid;
        #pragma unroll
        for (int nt = 0; nt < 16; ++nt) {
            const int d0 = nt * 8 + 2 * tg;
            *(float2*)&Hp[f0 * DDIM + d0]       =
                make_float2(acc[nt][0], acc[nt][1]);
            *(float2*)&Hp[(f0 + 8) * DDIM + d0] =
                make_float2(acc[nt][2], acc[nt][3]);
        }
    }
    __syncthreads();                 // smem reads done; reuse as scratch
    {
        float* Ssc = (float*)&smAh[0][0];
        Ssc[tid] = s_local;
        __syncthreads();
        if (tid < 128)
            g_partS[(chunk * NPAIR + pair) * FDIM + tid] =
                Ssc[tid] + Ssc[tid + 128];
    }

    // deterministic in-kernel reduction by the last-arriving chunk CTA
    __threadfence();
    if (tid == 0)
        s_is_last = (atomicAdd(&g_cnt[pair], 1) == CHUNKS - 1);
    __syncthreads();
    if (s_is_last) {
        __threadfence();
        const size_t NHp = (size_t)FDIM * DDIM;
        const float4* p0 = (const float4*)(g_partH + (0 * NPAIR + pair) * NHp);
        const float4* p1 = (const float4*)(g_partH + (1 * NPAIR + pair) * NHp);
        const float4* p2 = (const float4*)(g_partH + (2 * NPAIR + pair) * NHp);
        const float4* p3 = (const float4*)(g_partH + (3 * NPAIR + pair) * NHp);
        float* Ho = out + OFF_H + (size_t)pair * NHp;
        for (int i = tid; i < (int)(NHp / 4); i += 256) {
            float4 a = p0[i], b = p1[i], c = p2[i], d = p3[i];
            float4 r;
            r.x = ((a.x + b.x) + c.x) + d.x;
            r.y = ((a.y + b.y) + c.y) + d.y;
            r.z = ((a.z + b.z) + c.z) + d.z;
            r.w = ((a.w + b.w) + c.w) + d.w;
            stcs128(Ho + 4 * i, r);            // streaming: write-once output
        }
        if (tid < FDIM) {
            float s = 0.0f;
            #pragma unroll
            for (int c2 = 0; c2 < CHUNKS; ++c2)
                s += g_partS[(c2 * NPAIR + pair) * FDIM + tid];
            out[OFF_S + pair * FDIM + tid] = s;
        }
        if (tid == 0) g_cnt[pair] = 0;   // reset for next graph replay
    }
}

// ---------------------------------------------------------------------------
// Gather kernel (lean registers -> 3 CTAs/SM): 4 rows/warp, streaming stores.
// ---------------------------------------------------------------------------
__global__ void __launch_bounds__(256, 3) gather_kernel(
    const float* __restrict__ K_top, const float* __restrict__ V_top,
    const float* __restrict__ FK_top,
    const float* __restrict__ K_win, const float* __restrict__ V_win,
    const float* __restrict__ FK_win,
    float* __restrict__ out)
{
    const int tid  = threadIdx.x;
    const int warp = tid >> 5;
    const int lane = tid & 31;
    const int rowid0 = (blockIdx.x * 8 + warp) * 4;   // 4 consecutive rows
    const int pair   = rowid0 >> 11;
    const int gbase  = pair * NCAT + (rowid0 & (GDIM - 1));

    const float4 *ks[4], *vs[4], *fs[4];
    #pragma unroll
    for (int r = 0; r < 4; ++r) {
        const unsigned idx = g_order[gbase + r];
        if (idx < GDIM) {
            const size_t rr = (size_t)pair * GDIM + idx;
            ks[r] = (const float4*)(K_top + rr * 128);
            vs[r] = (const float4*)(V_top + rr * 128);
            fs[r] = (const float4*)(FK_top + rr * 128);
        } else {
            const size_t rr = (size_t)pair * CDIM + (idx - GDIM);
            ks[r] = (const float4*)(K_win + rr * 128);
            vs[r] = (const float4*)(V_win + rr * 128);
            fs[r] = (const float4*)(FK_win + rr * 128);
        }
    }
    float4 rk[4], rv[4], rf[4];
    #pragma unroll
    for (int r = 0; r < 4; ++r) {   // 12 independent loads in flight
        rk[r] = ks[r][lane]; rv[r] = vs[r][lane]; rf[r] = fs[r][lane];
    }
    #pragma unroll
    for (int r = 0; r < 4; ++r) {   // streaming stores: write-once output
        stcs128(out + OFF_K  + (size_t)(rowid0 + r) * 128 + 4 * lane, rk[r]);
        stcs128(out + OFF_V  + (size_t)(rowid0 + r) * 128 + 4 * lane, rv[r]);
        stcs128(out + OFF_FK + (size_t)(rowid0 + r) * 128 + 4 * lane, rf[r]);
    }
}

// ---------------------------------------------------------------------------
extern "C" void kernel_launch(void* const* d_in, const int* in_sizes, int n_in,
                              void* d_out, int out_size)
{
    const float* K_top      = (const float*)d_in[0];
    const float* V_top      = (const float*)d_in[1];
    const float* FK_top     = (const float*)d_in[2];
    const float* heap_score = (const float*)d_in[3];
    const float* K_win      = (const float*)d_in[4];
    const float* V_win      = (const float*)d_in[5];
    const float* FK_win     = (const float*)d_in[6];
    const float* win_score  = (const float*)d_in[7];
    float* out = (float*)d_out;

    cudaStream_t s2;
    cudaStreamCreateWithFlags(&s2, cudaStreamNonBlocking);
    cudaEvent_t e1, e2;
    cudaEventCreateWithFlags(&e1, cudaEventDisableTiming);
    cudaEventCreateWithFlags(&e2, cudaEventDisableTiming);

    sort_kernel<<<NPAIR * 2, 512>>>(heap_score, win_score, out + OFF_HEAP);

    // fork: gemm on s2, gather on the captured (default) stream — concurrent
    cudaEventRecord(e1, 0);
    cudaStreamWaitEvent(s2, e1, 0);
    gemm_kernel<<<NGEMM, 256, 0, s2>>>(V_top, FK_top, V_win, FK_win, out);
    gather_kernel<<<NGATHER, 256>>>(K_top, V_top, FK_top,
                                    K_win, V_win, FK_win, out);
    // join
    cudaEventRecord(e2, s2);
    cudaStreamWaitEvent(0, e2, 0);
}

// round 16
// speedup vs baseline: 1.1965x; 1.0050x over previous
#include <cuda_runtime.h>
#include <cuda_bf16.h>

// B=2, H=32, G=2048, C=2048, D=128, F=128
#define NPAIR 64
#define GDIM  2048
#define CDIM  2048
#define NCAT  4096
#define DDIM  128
#define FDIM  128

#define OFF_HEAP 0ULL
#define OFF_K    131072ULL
#define OFF_V    16908288ULL
#define OFF_FK   33685504ULL
#define OFF_H    50462720ULL
#define OFF_S    51511296ULL

#define CHUNKS  4
#define CHUNK_G 512            // CDIM / CHUNKS
#define KT      16             // g rows per tile
#define NT      (CHUNK_G / KT) // 32 tiles

#define NGEMM    (NPAIR * CHUNKS)          // 256 gemm CTAs
#define NGATHER  ((NPAIR * GDIM) / 32)     // 4096 gather CTAs (4 rows/warp)

#define ROWB   272                         // padded row: 128 bf16 + 8 pad (bytes)
#define TILEB  (KT * ROWB)                 // 4352 bytes per tile buffer

typedef unsigned long long ull;

__device__ unsigned int g_order[NPAIR * NCAT];
__device__ float g_partH[(size_t)CHUNKS * NPAIR * FDIM * DDIM];   // 16 MB
__device__ float g_partS[CHUNKS * NPAIR * FDIM];
__device__ int   g_cnt[NPAIR];             // zero-init; reset by last CTA

// ---------------------------------------------------------------------------
__device__ __forceinline__ unsigned int f2key_desc(float s) {
    unsigned int u = __float_as_uint(s);
    unsigned int us = (u & 0x80000000u) ? ~u : (u | 0x80000000u);
    return ~us;
}
__device__ __forceinline__ float key2f(unsigned int hi) {
    unsigned int us = ~hi;
    unsigned int u = (us & 0x80000000u) ? (us ^ 0x80000000u) : ~us;
    return __uint_as_float(u);
}
__device__ __forceinline__ void cswap(ull& a, ull& b, bool up) {
    if ((a > b) == up) { ull t = a; a = b; b = t; }
}
__device__ __forceinline__ ull dsmem_ld64(unsigned my_smem_addr, unsigned peer_rank) {
    unsigned remote;
    asm("mapa.shared::cluster.u32 %0, %1, %2;"
        : "=r"(remote) : "r"(my_smem_addr), "r"(peer_rank));
    ull v;
    asm volatile("ld.shared::cluster.b64 %0, [%1];" : "=l"(v) : "r"(remote));
    return v;
}
// streaming (evict-first) stores for write-once data
__device__ __forceinline__ void stcs128(float* p, float4 v) {
    asm volatile("st.global.cs.v4.f32 [%0], {%1,%2,%3,%4};"
                 :: "l"(p), "f"(v.x), "f"(v.y), "f"(v.z), "f"(v.w) : "memory");
}

// ---------------------------------------------------------------------------
// Cluster sort: 128 CTAs in 64 clusters of 2; half-sort, DSMEM exchange,
// local merge (half 0 only — bottom half needs only SET semantics for the
// gemm, so half 1 writes its indices right after the exchange and exits).
// Ping-pong smem buffers: ONE __syncthreads per smem stage (was two).
// ---------------------------------------------------------------------------
__global__ void __launch_bounds__(512) __cluster_dims__(2, 1, 1)
sort_kernel(const float* __restrict__ heap_score,
            const float* __restrict__ win_score,
            float* __restrict__ out_heap)
{
    __shared__ ull sk[2][2048];   // 32 KB ping-pong
    const int pair = blockIdx.x >> 1;
    const int half = blockIdx.x & 1;     // == cluster ctarank
    const int tid  = threadIdx.x;
    const bool desc = (half == 1);
    int pp = 0;

    float4 sc = (half == 0)
        ? ((const float4*)(heap_score + (size_t)pair * GDIM))[tid]
        : ((const float4*)(win_score  + (size_t)pair * CDIM))[tid];

    ull e[4];
    {
        const int p = half * 2048 + 4 * tid;
        e[0] = ((ull)f2key_desc(sc.x) << 32) | (unsigned)(p + 0);
        e[1] = ((ull)f2key_desc(sc.y) << 32) | (unsigned)(p + 1);
        e[2] = ((ull)f2key_desc(sc.z) << 32) | (unsigned)(p + 2);
        e[3] = ((ull)f2key_desc(sc.w) << 32) | (unsigned)(p + 3);
    }

    cswap(e[0], e[1], !desc);
    cswap(e[2], e[3], desc);

    for (int k = 4; k <= 2048; k <<= 1) {
        const bool up = (((tid & (k >> 2)) == 0) != desc);
        for (int j = k >> 1; j >= 4; j >>= 1) {
            if (j >= 128) {
                ull* buf = sk[pp];
                const int base = 4 * tid;
                buf[base + 0] = e[0]; buf[base + 1] = e[1];
                buf[base + 2] = e[2]; buf[base + 3] = e[3];
                __syncthreads();
                const int pt = (tid ^ (j >> 2)) * 4;
                const bool lower = ((tid & (j >> 2)) == 0);
                ull p0 = buf[pt], p1 = buf[pt + 1];
                ull p2 = buf[pt + 2], p3 = buf[pt + 3];
                if (lower == up) {
                    e[0] = e[0] < p0 ? e[0] : p0;  e[1] = e[1] < p1 ? e[1] : p1;
                    e[2] = e[2] < p2 ? e[2] : p2;  e[3] = e[3] < p3 ? e[3] : p3;
                } else {
                    e[0] = e[0] > p0 ? e[0] : p0;  e[1] = e[1] > p1 ? e[1] : p1;
                    e[2] = e[2] > p2 ? e[2] : p2;  e[3] = e[3] > p3 ? e[3] : p3;
                }
                pp ^= 1;   // next smem stage uses the other buffer (no 2nd sync)
            } else {
                const int w = j >> 2;
                const bool lower = ((tid & w) == 0);
                #pragma unroll
                for (int s = 0; s < 4; ++s) {
                    ull p = __shfl_xor_sync(0xffffffffu, e[s], w);
                    e[s] = (lower == up) ? (e[s] < p ? e[s] : p)
                                         : (e[s] > p ? e[s] : p);
                }
            }
        }
        cswap(e[0], e[2], up); cswap(e[1], e[3], up);
        cswap(e[0], e[1], up); cswap(e[2], e[3], up);
    }

    // publish sorted half for the peer (buffer sk[pp], same pp in both CTAs)
    {
        ull* buf = sk[pp];
        const int base = 4 * tid;
        buf[base + 0] = e[0]; buf[base + 1] = e[1];
        buf[base + 2] = e[2]; buf[base + 3] = e[3];
    }
    asm volatile("barrier.cluster.arrive.aligned;" ::: "memory");
    asm volatile("barrier.cluster.wait.aligned;" ::: "memory");
    {
        const unsigned peer = (unsigned)(half ^ 1);
        #pragma unroll
        for (int s = 0; s < 4; ++s) {
            const unsigned a =
                (unsigned)__cvta_generic_to_shared(&sk[pp][4 * tid + s]);
            ull p = dsmem_ld64(a, peer);
            if (half == 0) e[s] = e[s] < p ? e[s] : p;
            else           e[s] = e[s] > p ? e[s] : p;
        }
    }
    asm volatile("barrier.cluster.arrive.aligned;" ::: "memory");
    asm volatile("barrier.cluster.wait.aligned;" ::: "memory");
    pp ^= 1;

    const int mybase = pair * NCAT + half * 2048 + 4 * tid;

    if (half == 1) {
        // bottom half: SET semantics suffice for the gemm — write and exit
        g_order[mybase + 0] = (unsigned)e[0];
        g_order[mybase + 1] = (unsigned)e[1];
        g_order[mybase + 2] = (unsigned)e[2];
        g_order[mybase + 3] = (unsigned)e[3];
        return;
    }

    // half 0: local ascending bitonic merge (j = 1024..128 via smem, ping-pong)
    #pragma unroll
    for (int j = 1024; j >= 128; j >>= 1) {
        ull* buf = sk[pp];
        const int base = 4 * tid;
        buf[base + 0] = e[0]; buf[base + 1] = e[1];
        buf[base + 2] = e[2]; buf[base + 3] = e[3];
        __syncthreads();
        const int pt = (tid ^ (j >> 2)) * 4;
        const bool lower = ((tid & (j >> 2)) == 0);
        ull q0 = buf[pt], q1 = buf[pt + 1], q2 = buf[pt + 2], q3 = buf[pt + 3];
        if (lower) {
            e[0] = e[0] < q0 ? e[0] : q0;  e[1] = e[1] < q1 ? e[1] : q1;
            e[2] = e[2] < q2 ? e[2] : q2;  e[3] = e[3] < q3 ? e[3] : q3;
        } else {
            e[0] = e[0] > q0 ? e[0] : q0;  e[1] = e[1] > q1 ? e[1] : q1;
            e[2] = e[2] > q2 ? e[2] : q2;  e[3] = e[3] > q3 ? e[3] : q3;
        }
        pp ^= 1;
    }
    #pragma unroll
    for (int j = 64; j >= 4; j >>= 1) {
        const int w = j >> 2;
        const bool lower = ((tid & w) == 0);
        #pragma unroll
        for (int s = 0; s < 4; ++s) {
            ull q = __shfl_xor_sync(0xffffffffu, e[s], w);
            e[s] = lower ? (e[s] < q ? e[s] : q) : (e[s] > q ? e[s] : q);
        }
    }
    cswap(e[0], e[2], true); cswap(e[1], e[3], true);
    cswap(e[0], e[1], true); cswap(e[2], e[3], true);

    g_order[mybase + 0] = (unsigned)e[0];
    g_order[mybase + 1] = (unsigned)e[1];
    g_order[mybase + 2] = (unsigned)e[2];
    g_order[mybase + 3] = (unsigned)e[3];
    {
        float4 hs;
        hs.x = key2f((unsigned)(e[0] >> 32));
        hs.y = key2f((unsigned)(e[1] >> 32));
        hs.z = key2f((unsigned)(e[2] >> 32));
        hs.w = key2f((unsigned)(e[3] >> 32));
        ((float4*)(out_heap + (size_t)pair * GDIM))[tid] = hs;
    }
}

// ---------------------------------------------------------------------------
// mma helpers
// ---------------------------------------------------------------------------
__device__ __forceinline__ void ldsm4t(unsigned r[4], unsigned addr) {
    asm volatile(
        "ldmatrix.sync.aligned.m8n8.x4.trans.shared.b16 {%0,%1,%2,%3}, [%4];"
        : "=r"(r[0]), "=r"(r[1]), "=r"(r[2]), "=r"(r[3]) : "r"(addr));
}
__device__ __forceinline__ void mma16816(float c[4], const unsigned a[4],
                                         unsigned b0, unsigned b1) {
    asm volatile(
        "mma.sync.aligned.m16n8k16.row.col.f32.bf16.bf16.f32 "
        "{%0,%1,%2,%3}, {%4,%5,%6,%7}, {%8,%9}, {%0,%1,%2,%3};"
        : "+f"(c[0]), "+f"(c[1]), "+f"(c[2]), "+f"(c[3])
        : "r"(a[0]), "r"(a[1]), "r"(a[2]), "r"(a[3]), "r"(b0), "r"(b1));
}
__device__ __forceinline__ float bf16bits2f(unsigned short u) {
    return __uint_as_float(((unsigned)u) << 16);
}

// ---------------------------------------------------------------------------
// GEMM kernel (256 CTAs, CHUNKS=4): tensor-core bf16 3-pass split-K +
// in-kernel deterministic last-CTA reduction.
// ---------------------------------------------------------------------------
__global__ void __launch_bounds__(256, 2) gemm_kernel(
    const float* __restrict__ V_top, const float* __restrict__ FK_top,
    const float* __restrict__ V_win, const float* __restrict__ FK_win,
    float* __restrict__ out)
{
    __shared__ __align__(16) unsigned char smAh[2][TILEB];  // FK hi [g][f] bf16
    __shared__ __align__(16) unsigned char smAl[2][TILEB];  // FK lo
    __shared__ __align__(16) unsigned char smBh[2][TILEB];  // V  hi [g][d]
    __shared__ __align__(16) unsigned char smBl[2][TILEB];  // V  lo
    __shared__ unsigned s_idx[CHUNK_G];                     // 2 KB idx prefetch
    __shared__ int s_is_last;

    const int bid = blockIdx.x;
    const int tid = threadIdx.x;

    const int pair  = bid & (NPAIR - 1);
    const int chunk = bid >> 6;
    const int obase = pair * NCAT + GDIM + chunk * CHUNK_G;

    const int lane = tid & 31;
    const int warp = tid >> 5;            // m strip: f = warp*16..+15
    const int gg   = tid >> 4;            // staging row 0..15
    const int cc   = tid & 15;            // staging col group

    const int kk  = lane & 7;
    const int sel = lane >> 3;
    const unsigned offA = (unsigned)(((sel >> 1) * 8 + kk) * ROWB
                                     + (warp * 16 + (sel & 1) * 8) * 2);
    const unsigned offB = (unsigned)(((sel & 1) * 8 + kk) * ROWB
                                     + ((sel >> 1) * 8) * 2);

    const unsigned baseAh = (unsigned)__cvta_generic_to_shared(&smAh[0][0]);
    const unsigned baseAl = (unsigned)__cvta_generic_to_shared(&smAl[0][0]);
    const unsigned baseBh = (unsigned)__cvta_generic_to_shared(&smBh[0][0]);
    const unsigned baseBl = (unsigned)__cvta_generic_to_shared(&smBl[0][0]);

    // prefetch ALL chunk indices (off the per-tile critical path)
    s_idx[tid]       = g_order[obase + tid];
    s_idx[tid + 256] = g_order[obase + tid + 256];
    __syncthreads();

    float acc[16][4];
    #pragma unroll
    for (int i = 0; i < 16; ++i)
        #pragma unroll
        for (int j = 0; j < 4; ++j) acc[i][j] = 0.0f;
    float s_local = 0.0f;

    struct Stage { float4 f0, f1, v0, v1; };
    auto stage_ldg = [&](int kt) -> Stage {
        const unsigned idx = s_idx[kt * KT + gg];
        const float *fsrc, *vsrc;
        if (idx < GDIM) {
            const size_t r = (size_t)pair * GDIM + idx;
            fsrc = FK_top + r * FDIM;  vsrc = V_top + r * DDIM;
        } else {
            const size_t r = (size_t)pair * CDIM + (idx - GDIM);
            fsrc = FK_win + r * FDIM;  vsrc = V_win + r * DDIM;
        }
        Stage s;
        s.f0 = *(const float4*)(fsrc + 4 * cc);
        s.f1 = *(const float4*)(fsrc + 64 + 4 * cc);
        s.v0 = *(const float4*)(vsrc + 4 * cc);
        s.v1 = *(const float4*)(vsrc + 64 + 4 * cc);
        return s;
    };
    auto cvt_sts = [&](unsigned char* hi_buf, unsigned char* lo_buf,
                       float4 a, int byteoff) {
        __nv_bfloat162 h01 = __floats2bfloat162_rn(a.x, a.y);
        __nv_bfloat162 h23 = __floats2bfloat162_rn(a.z, a.w);
        float r0 = __low2float(h01), r1 = __high2float(h01);
        float r2 = __low2float(h23), r3 = __high2float(h23);
        __nv_bfloat162 l01 = __floats2bfloat162_rn(a.x - r0, a.y - r1);
        __nv_bfloat162 l23 = __floats2bfloat162_rn(a.z - r2, a.w - r3);
        *(uint2*)(hi_buf + byteoff) =
            make_uint2(*(unsigned*)&h01, *(unsigned*)&h23);
        *(uint2*)(lo_buf + byteoff) =
            make_uint2(*(unsigned*)&l01, *(unsigned*)&l23);
    };
    auto stage_sts = [&](int buf, const Stage& s) {
        const int bo = gg * ROWB + cc * 8;
        cvt_sts(smAh[buf], smAl[buf], s.f0, bo);
        cvt_sts(smAh[buf], smAl[buf], s.f1, bo + 128);
        cvt_sts(smBh[buf], smBl[buf], s.v0, bo);
        cvt_sts(smBh[buf], smBl[buf], s.v1, bo + 128);
    };

    Stage st = stage_ldg(0);
    stage_sts(0, st);

    for (int kt = 0; kt < NT; ++kt) {
        const int buf = kt & 1;
        if (kt + 1 < NT) st = stage_ldg(kt + 1);   // LDG early
        __syncthreads();                           // tile kt smem ready

        const unsigned bufo = (unsigned)(buf * TILEB);
        unsigned Ah[4], Al[4];
        ldsm4t(Ah, baseAh + bufo + offA);
        ldsm4t(Al, baseAl + bufo + offA);

        #pragma unroll
        for (int np = 0; np < 8; ++np) {
            unsigned Bh[4], Bl[4];
            const unsigned nb = (unsigned)(np * 32);
            ldsm4t(Bh, baseBh + bufo + offB + nb);
            ldsm4t(Bl, baseBl + bufo + offB + nb);
            mma16816(acc[2 * np],     Ah, Bh[0], Bh[1]);
            mma16816(acc[2 * np + 1], Ah, Bh[2], Bh[3]);
            mma16816(acc[2 * np],     Ah, Bl[0], Bl[1]);
            mma16816(acc[2 * np + 1], Ah, Bl[2], Bl[3]);
            mma16816(acc[2 * np],     Al, Bh[0], Bh[1]);
            mma16816(acc[2 * np + 1], Al, Bh[2], Bh[3]);
        }

        {
            const int f = tid & 127;
            const unsigned char* src = (tid < 128) ? smAh[buf] : smAl[buf];
            #pragma unroll
            for (int g = 0; g < KT; ++g)
                s_local += bf16bits2f(*(const unsigned short*)
                                      (src + g * ROWB + f * 2));
        }

        if (kt + 1 < NT) stage_sts(buf ^ 1, st);
    }

    // write split-K partials (normal stores: re-read once by last CTA via L2)
    float* Hp = g_partH + ((size_t)(chunk * NPAIR + pair)) * (FDIM * DDIM);
    {
        const int gid = lane >> 2, tg = lane & 3;
        const int f0 = warp * 16 + gid;
        #pragma unroll
        for (int nt = 0; nt < 16; ++nt) {
            const int d0 = nt * 8 + 2 * tg;
            *(float2*)&Hp[f0 * DDIM + d0]       =
                make_float2(acc[nt][0], acc[nt][1]);
            *(float2*)&Hp[(f0 + 8) * DDIM + d0] =
                make_float2(acc[nt][2], acc[nt][3]);
        }
    }
    __syncthreads();                 // smem reads done; reuse as scratch
    {
        float* Ssc = (float*)&smAh[0][0];
        Ssc[tid] = s_local;
        __syncthreads();
        if (tid < 128)
            g_partS[(chunk * NPAIR + pair) * FDIM + tid] =
                Ssc[tid] + Ssc[tid + 128];
    }

    // deterministic in-kernel reduction by the last-arriving chunk CTA
    __threadfence();
    if (tid == 0)
        s_is_last = (atomicAdd(&g_cnt[pair], 1) == CHUNKS - 1);
    __syncthreads();
    if (s_is_last) {
        __threadfence();
        const size_t NHp = (size_t)FDIM * DDIM;
        const float4* p0 = (const float4*)(g_partH + (0 * NPAIR + pair) * NHp);
        const float4* p1 = (const float4*)(g_partH + (1 * NPAIR + pair) * NHp);
        const float4* p2 = (const float4*)(g_partH + (2 * NPAIR + pair) * NHp);
        const float4* p3 = (const float4*)(g_partH + (3 * NPAIR + pair) * NHp);
        float* Ho = out + OFF_H + (size_t)pair * NHp;
        for (int i = tid; i < (int)(NHp / 4); i += 256) {
            float4 a = p0[i], b = p1[i], c = p2[i], d = p3[i];
            float4 r;
            r.x = ((a.x + b.x) + c.x) + d.x;
            r.y = ((a.y + b.y) + c.y) + d.y;
            r.z = ((a.z + b.z) + c.z) + d.z;
            r.w = ((a.w + b.w) + c.w) + d.w;
            stcs128(Ho + 4 * i, r);            // streaming: write-once output
        }
        if (tid < FDIM) {
            float s = 0.0f;
            #pragma unroll
            for (int c2 = 0; c2 < CHUNKS; ++c2)
                s += g_partS[(c2 * NPAIR + pair) * FDIM + tid];
            out[OFF_S + pair * FDIM + tid] = s;
        }
        if (tid == 0) g_cnt[pair] = 0;   // reset for next graph replay
    }
}

// ---------------------------------------------------------------------------
// Gather kernel (lean registers -> 3 CTAs/SM): 4 rows/warp, streaming stores.
// ---------------------------------------------------------------------------
__global__ void __launch_bounds__(256, 3) gather_kernel(
    const float* __restrict__ K_top, const float* __restrict__ V_top,
    const float* __restrict__ FK_top,
    const float* __restrict__ K_win, const float* __restrict__ V_win,
    const float* __restrict__ FK_win,
    float* __restrict__ out)
{
    const int tid  = threadIdx.x;
    const int warp = tid >> 5;
    const int lane = tid & 31;
    const int rowid0 = (blockIdx.x * 8 + warp) * 4;   // 4 consecutive rows
    const int pair   = rowid0 >> 11;
    const int gbase  = pair * NCAT + (rowid0 & (GDIM - 1));

    const float4 *ks[4], *vs[4], *fs[4];
    #pragma unroll
    for (int r = 0; r < 4; ++r) {
        const unsigned idx = g_order[gbase + r];
        if (idx < GDIM) {
            const size_t rr = (size_t)pair * GDIM + idx;
            ks[r] = (const float4*)(K_top + rr * 128);
            vs[r] = (const float4*)(V_top + rr * 128);
            fs[r] = (const float4*)(FK_top + rr * 128);
        } else {
            const size_t rr = (size_t)pair * CDIM + (idx - GDIM);
            ks[r] = (const float4*)(K_win + rr * 128);
            vs[r] = (const float4*)(V_win + rr * 128);
            fs[r] = (const float4*)(FK_win + rr * 128);
        }
    }
    float4 rk[4], rv[4], rf[4];
    #pragma unroll
    for (int r = 0; r < 4; ++r) {   // 12 independent loads in flight
        rk[r] = ks[r][lane]; rv[r] = vs[r][lane]; rf[r] = fs[r][lane];
    }
    #pragma unroll
    for (int r = 0; r < 4; ++r) {   // streaming stores: write-once output
        stcs128(out + OFF_K  + (size_t)(rowid0 + r) * 128 + 4 * lane, rk[r]);
        stcs128(out + OFF_V  + (size_t)(rowid0 + r) * 128 + 4 * lane, rv[r]);
        stcs128(out + OFF_FK + (size_t)(rowid0 + r) * 128 + 4 * lane, rf[r]);
    }
}

// ---------------------------------------------------------------------------
extern "C" void kernel_launch(void* const* d_in, const int* in_sizes, int n_in,
                              void* d_out, int out_size)
{
    const float* K_top      = (const float*)d_in[0];
    const float* V_top      = (const float*)d_in[1];
    const float* FK_top     = (const float*)d_in[2];
    const float* heap_score = (const float*)d_in[3];
    const float* K_win      = (const float*)d_in[4];
    const float* V_win      = (const float*)d_in[5];
    const float* FK_win     = (const float*)d_in[6];
    const float* win_score  = (const float*)d_in[7];
    float* out = (float*)d_out;

    cudaStream_t s2;
    cudaStreamCreateWithFlags(&s2, cudaStreamNonBlocking);
    cudaEvent_t e1, e2;
    cudaEventCreateWithFlags(&e1, cudaEventDisableTiming);
    cudaEventCreateWithFlags(&e2, cudaEventDisableTiming);

    sort_kernel<<<NPAIR * 2, 512>>>(heap_score, win_score, out + OFF_HEAP);

    // fork: gemm on s2, gather on the captured (default) stream — concurrent
    cudaEventRecord(e1, 0);
    cudaStreamWaitEvent(s2, e1, 0);
    gemm_kernel<<<NGEMM, 256, 0, s2>>>(V_top, FK_top, V_win, FK_win, out);
    gather_kernel<<<NGATHER, 256>>>(K_top, V_top, FK_top,
                                    K_win, V_win, FK_win, out);
    // join
    cudaEventRecord(e2, s2);
    cudaStreamWaitEvent(0, e2, 0);
}

// round 17
// speedup vs baseline: 1.1968x; 1.0003x over previous
#include <cuda_runtime.h>
#include <cuda_bf16.h>

// B=2, H=32, G=2048, C=2048, D=128, F=128
#define NPAIR 64
#define GDIM  2048
#define CDIM  2048
#define NCAT  4096
#define DDIM  128
#define FDIM  128

#define OFF_HEAP 0ULL
#define OFF_K    131072ULL
#define OFF_V    16908288ULL
#define OFF_FK   33685504ULL
#define OFF_H    50462720ULL
#define OFF_S    51511296ULL

#define CHUNKS  4
#define CHUNK_G 512            // CDIM / CHUNKS
#define KT      16             // g rows per tile
#define NT      (CHUNK_G / KT) // 32 tiles

#define NGEMM    (NPAIR * CHUNKS)          // 256 gemm CTAs
#define NGATHER  ((NPAIR * GDIM) / 32)     // 4096 gather CTAs (4 rows/warp)

#define ROWB   272                         // padded row: 128 bf16 + 8 pad (bytes)
#define TILEB  (KT * ROWB)                 // 4352 bytes per tile buffer

typedef unsigned long long ull;

__device__ unsigned int g_order[NPAIR * NCAT];
__device__ float g_partH[(size_t)CHUNKS * NPAIR * FDIM * DDIM];   // 16 MB
__device__ float g_partS[CHUNKS * NPAIR * FDIM];
__device__ int   g_cnt[NPAIR];             // zero-init; reset by last CTA

// ---------------------------------------------------------------------------
__device__ __forceinline__ unsigned int f2key_desc(float s) {
    unsigned int u = __float_as_uint(s);
    unsigned int us = (u & 0x80000000u) ? ~u : (u | 0x80000000u);
    return ~us;
}
__device__ __forceinline__ float key2f(unsigned int hi) {
    unsigned int us = ~hi;
    unsigned int u = (us & 0x80000000u) ? (us ^ 0x80000000u) : ~us;
    return __uint_as_float(u);
}
__device__ __forceinline__ void cswap(ull& a, ull& b, bool up) {
    if ((a > b) == up) { ull t = a; a = b; b = t; }
}
__device__ __forceinline__ ull dsmem_ld64(unsigned my_smem_addr, unsigned peer_rank) {
    unsigned remote;
    asm("mapa.shared::cluster.u32 %0, %1, %2;"
        : "=r"(remote) : "r"(my_smem_addr), "r"(peer_rank));
    ull v;
    asm volatile("ld.shared::cluster.b64 %0, [%1];" : "=l"(v) : "r"(remote));
    return v;
}
// streaming (evict-first) stores for write-once data
__device__ __forceinline__ void stcs128(float* p, float4 v) {
    asm volatile("st.global.cs.v4.f32 [%0], {%1,%2,%3,%4};"
                 :: "l"(p), "f"(v.x), "f"(v.y), "f"(v.z), "f"(v.w) : "memory");
}

// ---------------------------------------------------------------------------
// Cluster sort: 128 CTAs in 64 clusters of 2; half-sort, DSMEM exchange,
// local merge (half 0 only; half 1 writes set-order bottom indices and exits).
// Ping-pong smem (1 sync per stage) + 128-bit vectorized smem traffic.
// ---------------------------------------------------------------------------
__global__ void __launch_bounds__(512) __cluster_dims__(2, 1, 1)
sort_kernel(const float* __restrict__ heap_score,
            const float* __restrict__ win_score,
            float* __restrict__ out_heap)
{
    __shared__ __align__(16) ull sk[2][2048];   // 32 KB ping-pong
    const int pair = blockIdx.x >> 1;
    const int half = blockIdx.x & 1;     // == cluster ctarank
    const int tid  = threadIdx.x;
    const bool desc = (half == 1);
    const int base = 4 * tid;            // stage-invariant
    int pp = 0;

    float4 sc = (half == 0)
        ? ((const float4*)(heap_score + (size_t)pair * GDIM))[tid]
        : ((const float4*)(win_score  + (size_t)pair * CDIM))[tid];

    ull e[4];
    {
        const int p = half * 2048 + base;
        e[0] = ((ull)f2key_desc(sc.x) << 32) | (unsigned)(p + 0);
        e[1] = ((ull)f2key_desc(sc.y) << 32) | (unsigned)(p + 1);
        e[2] = ((ull)f2key_desc(sc.z) << 32) | (unsigned)(p + 2);
        e[3] = ((ull)f2key_desc(sc.w) << 32) | (unsigned)(p + 3);
    }

    cswap(e[0], e[1], !desc);
    cswap(e[2], e[3], desc);

    for (int k = 4; k <= 2048; k <<= 1) {
        const bool up = (((tid & (k >> 2)) == 0) != desc);
        for (int j = k >> 1; j >= 4; j >>= 1) {
            if (j >= 128) {
                ull* buf = sk[pp];
                *(ulonglong2*)&buf[base]     = make_ulonglong2(e[0], e[1]);
                *(ulonglong2*)&buf[base + 2] = make_ulonglong2(e[2], e[3]);
                __syncthreads();
                const int pt = (tid ^ (j >> 2)) * 4;
                const bool lower = ((tid & (j >> 2)) == 0);
                const ulonglong2 pa = *(const ulonglong2*)&buf[pt];
                const ulonglong2 pb = *(const ulonglong2*)&buf[pt + 2];
                if (lower == up) {
                    e[0] = e[0] < pa.x ? e[0] : pa.x;
                    e[1] = e[1] < pa.y ? e[1] : pa.y;
                    e[2] = e[2] < pb.x ? e[2] : pb.x;
                    e[3] = e[3] < pb.y ? e[3] : pb.y;
                } else {
                    e[0] = e[0] > pa.x ? e[0] : pa.x;
                    e[1] = e[1] > pa.y ? e[1] : pa.y;
                    e[2] = e[2] > pb.x ? e[2] : pb.x;
                    e[3] = e[3] > pb.y ? e[3] : pb.y;
                }
                pp ^= 1;   // next stage uses the other buffer (no 2nd sync)
            } else {
                const int w = j >> 2;
                const bool lower = ((tid & w) == 0);
                #pragma unroll
                for (int s = 0; s < 4; ++s) {
                    ull p = __shfl_xor_sync(0xffffffffu, e[s], w);
                    e[s] = (lower == up) ? (e[s] < p ? e[s] : p)
                                         : (e[s] > p ? e[s] : p);
                }
            }
        }
        cswap(e[0], e[2], up); cswap(e[1], e[3], up);
        cswap(e[0], e[1], up); cswap(e[2], e[3], up);
    }

    // publish sorted half for the peer (both CTAs have the same pp here)
    {
        ull* buf = sk[pp];
        *(ulonglong2*)&buf[base]     = make_ulonglong2(e[0], e[1]);
        *(ulonglong2*)&buf[base + 2] = make_ulonglong2(e[2], e[3]);
    }
    asm volatile("barrier.cluster.arrive.aligned;" ::: "memory");
    asm volatile("barrier.cluster.wait.aligned;" ::: "memory");
    {
        const unsigned peer = (unsigned)(half ^ 1);
        #pragma unroll
        for (int s = 0; s < 4; ++s) {
            const unsigned a =
                (unsigned)__cvta_generic_to_shared(&sk[pp][base + s]);
            ull p = dsmem_ld64(a, peer);
            if (half == 0) e[s] = e[s] < p ? e[s] : p;
            else           e[s] = e[s] > p ? e[s] : p;
        }
    }
    asm volatile("barrier.cluster.arrive.aligned;" ::: "memory");
    asm volatile("barrier.cluster.wait.aligned;" ::: "memory");
    pp ^= 1;

    const int mybase = pair * NCAT + half * 2048 + base;

    if (half == 1) {
        // bottom half: SET semantics suffice for the gemm — write and exit
        *(uint4*)&g_order[mybase] = make_uint4(
            (unsigned)e[0], (unsigned)e[1], (unsigned)e[2], (unsigned)e[3]);
        return;
    }

    // half 0: local ascending bitonic merge (j = 1024..128 via smem)
    #pragma unroll
    for (int j = 1024; j >= 128; j >>= 1) {
        ull* buf = sk[pp];
        *(ulonglong2*)&buf[base]     = make_ulonglong2(e[0], e[1]);
        *(ulonglong2*)&buf[base + 2] = make_ulonglong2(e[2], e[3]);
        __syncthreads();
        const int pt = (tid ^ (j >> 2)) * 4;
        const bool lower = ((tid & (j >> 2)) == 0);
        const ulonglong2 qa = *(const ulonglong2*)&buf[pt];
        const ulonglong2 qb = *(const ulonglong2*)&buf[pt + 2];
        if (lower) {
            e[0] = e[0] < qa.x ? e[0] : qa.x;
            e[1] = e[1] < qa.y ? e[1] : qa.y;
            e[2] = e[2] < qb.x ? e[2] : qb.x;
            e[3] = e[3] < qb.y ? e[3] : qb.y;
        } else {
            e[0] = e[0] > qa.x ? e[0] : qa.x;
            e[1] = e[1] > qa.y ? e[1] : qa.y;
            e[2] = e[2] > qb.x ? e[2] : qb.x;
            e[3] = e[3] > qb.y ? e[3] : qb.y;
        }
        pp ^= 1;
    }
    #pragma unroll
    for (int j = 64; j >= 4; j >>= 1) {
        const int w = j >> 2;
        const bool lower = ((tid & w) == 0);
        #pragma unroll
        for (int s = 0; s < 4; ++s) {
            ull q = __shfl_xor_sync(0xffffffffu, e[s], w);
            e[s] = lower ? (e[s] < q ? e[s] : q) : (e[s] > q ? e[s] : q);
        }
    }
    cswap(e[0], e[2], true); cswap(e[1], e[3], true);
    cswap(e[0], e[1], true); cswap(e[2], e[3], true);

    // stores issued back-to-back (independent; STG latency overlaps)
    *(uint4*)&g_order[mybase] = make_uint4(
        (unsigned)e[0], (unsigned)e[1], (unsigned)e[2], (unsigned)e[3]);
    {
        float4 hs;
        hs.x = key2f((unsigned)(e[0] >> 32));
        hs.y = key2f((unsigned)(e[1] >> 32));
        hs.z = key2f((unsigned)(e[2] >> 32));
        hs.w = key2f((unsigned)(e[3] >> 32));
        ((float4*)(out_heap + (size_t)pair * GDIM))[tid] = hs;
    }
}

// ---------------------------------------------------------------------------
// mma helpers
// ---------------------------------------------------------------------------
__device__ __forceinline__ void ldsm4t(unsigned r[4], unsigned addr) {
    asm volatile(
        "ldmatrix.sync.aligned.m8n8.x4.trans.shared.b16 {%0,%1,%2,%3}, [%4];"
        : "=r"(r[0]), "=r"(r[1]), "=r"(r[2]), "=r"(r[3]) : "r"(addr));
}
__device__ __forceinline__ void mma16816(float c[4], const unsigned a[4],
                                         unsigned b0, unsigned b1) {
    asm volatile(
        "mma.sync.aligned.m16n8k16.row.col.f32.bf16.bf16.f32 "
        "{%0,%1,%2,%3}, {%4,%5,%6,%7}, {%8,%9}, {%0,%1,%2,%3};"
        : "+f"(c[0]), "+f"(c[1]), "+f"(c[2]), "+f"(c[3])
        : "r"(a[0]), "r"(a[1]), "r"(a[2]), "r"(a[3]), "r"(b0), "r"(b1));
}
__device__ __forceinline__ float bf16bits2f(unsigned short u) {
    return __uint_as_float(((unsigned)u) << 16);
}

// ---------------------------------------------------------------------------
// GEMM kernel (256 CTAs, CHUNKS=4): tensor-core bf16 3-pass split-K +
// in-kernel deterministic last-CTA reduction.
// ---------------------------------------------------------------------------
__global__ void __launch_bounds__(256, 2) gemm_kernel(
    const float* __restrict__ V_top, const float* __restrict__ FK_top,
    const float* __restrict__ V_win, const float* __restrict__ FK_win,
    float* __restrict__ out)
{
    __shared__ __align__(16) unsigned char smAh[2][TILEB];  // FK hi [g][f] bf16
    __shared__ __align__(16) unsigned char smAl[2][TILEB];  // FK lo
    __shared__ __align__(16) unsigned char smBh[2][TILEB];  // V  hi [g][d]
    __shared__ __align__(16) unsigned char smBl[2][TILEB];  // V  lo
    __shared__ unsigned s_idx[CHUNK_G];                     // 2 KB idx prefetch
    __shared__ int s_is_last;

    const int bid = blockIdx.x;
    const int tid = threadIdx.x;

    const int pair  = bid & (NPAIR - 1);
    const int chunk = bid >> 6;
    const int obase = pair * NCAT + GDIM + chunk * CHUNK_G;

    const int lane = tid & 31;
    const int warp = tid >> 5;            // m strip: f = warp*16..+15
    const int gg   = tid >> 4;            // staging row 0..15
    const int cc   = tid & 15;            // staging col group

    const int kk  = lane & 7;
    const int sel = lane >> 3;
    const unsigned offA = (unsigned)(((sel >> 1) * 8 + kk) * ROWB
                                     + (warp * 16 + (sel & 1) * 8) * 2);
    const unsigned offB = (unsigned)(((sel & 1) * 8 + kk) * ROWB
                                     + ((sel >> 1) * 8) * 2);

    const unsigned baseAh = (unsigned)__cvta_generic_to_shared(&smAh[0][0]);
    const unsigned baseAl = (unsigned)__cvta_generic_to_shared(&smAl[0][0]);
    const unsigned baseBh = (unsigned)__cvta_generic_to_shared(&smBh[0][0]);
    const unsigned baseBl = (unsigned)__cvta_generic_to_shared(&smBl[0][0]);

    // prefetch ALL chunk indices (off the per-tile critical path)
    s_idx[tid]       = g_order[obase + tid];
    s_idx[tid + 256] = g_order[obase + tid + 256];
    __syncthreads();

    float acc[16][4];
    #pragma unroll
    for (int i = 0; i < 16; ++i)
        #pragma unroll
        for (int j = 0; j < 4; ++j) acc[i][j] = 0.0f;
    float s_local = 0.0f;

    struct Stage { float4 f0, f1, v0, v1; };
    auto stage_ldg = [&](int kt) -> Stage {
        const unsigned idx = s_idx[kt * KT + gg];
        const float *fsrc, *vsrc;
        if (idx < GDIM) {
            const size_t r = (size_t)pair * GDIM + idx;
            fsrc = FK_top + r * FDIM;  vsrc = V_top + r * DDIM;
        } else {
            const size_t r = (size_t)pair * CDIM + (idx - GDIM);
            fsrc = FK_win + r * FDIM;  vsrc = V_win + r * DDIM;
        }
        Stage s;
        s.f0 = *(const float4*)(fsrc + 4 * cc);
        s.f1 = *(const float4*)(fsrc + 64 + 4 * cc);
        s.v0 = *(const float4*)(vsrc + 4 * cc);
        s.v1 = *(const float4*)(vsrc + 64 + 4 * cc);
        return s;
    };
    auto cvt_sts = [&](unsigned char* hi_buf, unsigned char* lo_buf,
                       float4 a, int byteoff) {
        __nv_bfloat162 h01 = __floats2bfloat162_rn(a.x, a.y);
        __nv_bfloat162 h23 = __floats2bfloat162_rn(a.z, a.w);
        float r0 = __low2float(h01), r1 = __high2float(h01);
        float r2 = __low2float(h23), r3 = __high2float(h23);
        __nv_bfloat162 l01 = __floats2bfloat162_rn(a.x - r0, a.y - r1);
        __nv_bfloat162 l23 = __floats2bfloat162_rn(a.z - r2, a.w - r3);
        *(uint2*)(hi_buf + byteoff) =
            make_uint2(*(unsigned*)&h01, *(unsigned*)&h23);
        *(uint2*)(lo_buf + byteoff) =
            make_uint2(*(unsigned*)&l01, *(unsigned*)&l23);
    };
    auto stage_sts = [&](int buf, const Stage& s) {
        const int bo = gg * ROWB + cc * 8;
        cvt_sts(smAh[buf], smAl[buf], s.f0, bo);
        cvt_sts(smAh[buf], smAl[buf], s.f1, bo + 128);
        cvt_sts(smBh[buf], smBl[buf], s.v0, bo);
        cvt_sts(smBh[buf], smBl[buf], s.v1, bo + 128);
    };

    Stage st = stage_ldg(0);
    stage_sts(0, st);

    for (int kt = 0; kt < NT; ++kt) {
        const int buf = kt & 1;
        if (kt + 1 < NT) st = stage_ldg(kt + 1);   // LDG early
        __syncthreads();                           // tile kt smem ready

        const unsigned bufo = (unsigned)(buf * TILEB);
        unsigned Ah[4], Al[4];
        ldsm4t(Ah, baseAh + bufo + offA);
        ldsm4t(Al, baseAl + bufo + offA);

        #pragma unroll
        for (int np = 0; np < 8; ++np) {
            unsigned Bh[4], Bl[4];
            const unsigned nb = (unsigned)(np * 32);
            ldsm4t(Bh, baseBh + bufo + offB + nb);
            ldsm4t(Bl, baseBl + bufo + offB + nb);
            mma16816(acc[2 * np],     Ah, Bh[0], Bh[1]);
            mma16816(acc[2 * np + 1], Ah, Bh[2], Bh[3]);
            mma16816(acc[2 * np],     Ah, Bl[0], Bl[1]);
            mma16816(acc[2 * np + 1], Ah, Bl[2], Bl[3]);
            mma16816(acc[2 * np],     Al, Bh[0], Bh[1]);
            mma16816(acc[2 * np + 1], Al, Bh[2], Bh[3]);
        }

        {
            const int f = tid & 127;
            const unsigned char* src = (tid < 128) ? smAh[buf] : smAl[buf];
            #pragma unroll
            for (int g = 0; g < KT; ++g)
                s_local += bf16bits2f(*(const unsigned short*)
                                      (src + g * ROWB + f * 2));
        }

        if (kt + 1 < NT) stage_sts(buf ^ 1, st);
    }

    // write split-K partials (normal stores: re-read once by last CTA via L2)
    float* Hp = g_partH + ((size_t)(chunk * NPAIR + pair)) * (FDIM * DDIM);
    {
        const int gid = lane >> 2, tg = lane & 3;
        const int f0 = warp * 16 + gid;
        #pragma unroll
        for (int nt = 0; nt < 16; ++nt) {
            const int d0 = nt * 8 + 2 * tg;
            *(float2*)&Hp[f0 * DDIM + d0]       =
                make_float2(acc[nt][0], acc[nt][1]);
            *(float2*)&Hp[(f0 + 8) * DDIM + d0] =
                make_float2(acc[nt][2], acc[nt][3]);
        }
    }
    __syncthreads();                 // smem reads done; reuse as scratch
    {
        float* Ssc = (float*)&smAh[0][0];
        Ssc[tid] = s_local;
        __syncthreads();
        if (tid < 128)
            g_partS[(chunk * NPAIR + pair) * FDIM + tid] =
                Ssc[tid] + Ssc[tid + 128];
    }

    // deterministic in-kernel reduction by the last-arriving chunk CTA
    __threadfence();
    if (tid == 0)
        s_is_last = (atomicAdd(&g_cnt[pair], 1) == CHUNKS - 1);
    __syncthreads();
    if (s_is_last) {
        __threadfence();
        const size_t NHp = (size_t)FDIM * DDIM;
        const float4* p0 = (const float4*)(g_partH + (0 * NPAIR + pair) * NHp);
        const float4* p1 = (const float4*)(g_partH + (1 * NPAIR + pair) * NHp);
        const float4* p2 = (const float4*)(g_partH + (2 * NPAIR + pair) * NHp);
        const float4* p3 = (const float4*)(g_partH + (3 * NPAIR + pair) * NHp);
        float* Ho = out + OFF_H + (size_t)pair * NHp;
        for (int i = tid; i < (int)(NHp / 4); i += 256) {
            float4 a = p0[i], b = p1[i], c = p2[i], d = p3[i];
            float4 r;
            r.x = ((a.x + b.x) + c.x) + d.x;
            r.y = ((a.y + b.y) + c.y) + d.y;
            r.z = ((a.z + b.z) + c.z) + d.z;
            r.w = ((a.w + b.w) + c.w) + d.w;
            stcs128(Ho + 4 * i, r);            // streaming: write-once output
        }
        if (tid < FDIM) {
            float s = 0.0f;
            #pragma unroll
            for (int c2 = 0; c2 < CHUNKS; ++c2)
                s += g_partS[(c2 * NPAIR + pair) * FDIM + tid];
            out[OFF_S + pair * FDIM + tid] = s;
        }
        if (tid == 0) g_cnt[pair] = 0;   // reset for next graph replay
    }
}

// ---------------------------------------------------------------------------
// Gather kernel (lean registers -> 3 CTAs/SM): 4 rows/warp, streaming stores.
// ---------------------------------------------------------------------------
__global__ void __launch_bounds__(256, 3) gather_kernel(
    const float* __restrict__ K_top, const float* __restrict__ V_top,
    const float* __restrict__ FK_top,
    const float* __restrict__ K_win, const float* __restrict__ V_win,
    const float* __restrict__ FK_win,
    float* __restrict__ out)
{
    const int tid  = threadIdx.x;
    const int warp = tid >> 5;
    const int lane = tid & 31;
    const int rowid0 = (blockIdx.x * 8 + warp) * 4;   // 4 consecutive rows
    const int pair   = rowid0 >> 11;
    const int gbase  = pair * NCAT + (rowid0 & (GDIM - 1));

    const float4 *ks[4], *vs[4], *fs[4];
    #pragma unroll
    for (int r = 0; r < 4; ++r) {
        const unsigned idx = g_order[gbase + r];
        if (idx < GDIM) {
            const size_t rr = (size_t)pair * GDIM + idx;
            ks[r] = (const float4*)(K_top + rr * 128);
            vs[r] = (const float4*)(V_top + rr * 128);
            fs[r] = (const float4*)(FK_top + rr * 128);
        } else {
            const size_t rr = (size_t)pair * CDIM + (idx - GDIM);
            ks[r] = (const float4*)(K_win + rr * 128);
            vs[r] = (const float4*)(V_win + rr * 128);
            fs[r] = (const float4*)(FK_win + rr * 128);
        }
    }
    float4 rk[4], rv[4], rf[4];
    #pragma unroll
    for (int r = 0; r < 4; ++r) {   // 12 independent loads in flight
        rk[r] = ks[r][lane]; rv[r] = vs[r][lane]; rf[r] = fs[r][lane];
    }
    #pragma unroll
    for (int r = 0; r < 4; ++r) {   // streaming stores: write-once output
        stcs128(out + OFF_K  + (size_t)(rowid0 + r) * 128 + 4 * lane, rk[r]);
        stcs128(out + OFF_V  + (size_t)(rowid0 + r) * 128 + 4 * lane, rv[r]);
        stcs128(out + OFF_FK + (size_t)(rowid0 + r) * 128 + 4 * lane, rf[r]);
    }
}

// ---------------------------------------------------------------------------
extern "C" void kernel_launch(void* const* d_in, const int* in_sizes, int n_in,
                              void* d_out, int out_size)
{
    const float* K_top      = (const float*)d_in[0];
    const float* V_top      = (const float*)d_in[1];
    const float* FK_top     = (const float*)d_in[2];
    const float* heap_score = (const float*)d_in[3];
    const float* K_win      = (const float*)d_in[4];
    const float* V_win      = (const float*)d_in[5];
    const float* FK_win     = (const float*)d_in[6];
    const float* win_score  = (const float*)d_in[7];
    float* out = (float*)d_out;

    cudaStream_t s2;
    cudaStreamCreateWithFlags(&s2, cudaStreamNonBlocking);
    cudaEvent_t e1, e2;
    cudaEventCreateWithFlags(&e1, cudaEventDisableTiming);
    cudaEventCreateWithFlags(&e2, cudaEventDisableTiming);

    sort_kernel<<<NPAIR * 2, 512>>>(heap_score, win_score, out + OFF_HEAP);

    // fork: gemm on s2, gather on the captured (default) stream — concurrent
    cudaEventRecord(e1, 0);
    cudaStreamWaitEvent(s2, e1, 0);
    gemm_kernel<<<NGEMM, 256, 0, s2>>>(V_top, FK_top, V_win, FK_win, out);
    gather_kernel<<<NGATHER, 256>>>(K_top, V_top, FK_top,
                                    K_win, V_win, FK_win, out);
    // join
    cudaEventRecord(e2, s2);
    cudaStreamWaitEvent(0, e2, 0);
}